// round 2
// baseline (speedup 1.0000x reference)
#include <cuda_runtime.h>

// FilteredLeakyReLU: FIR 2x upsample -> lrelu(0.01) -> FIR 2x downsample, fused.
// x: [1024, 130, 130] f32 (B*C collapsed), filters: 12 taps each (symmetric).
// out: [1024, 128, 128] f32.
//
// Geometry (per dim):
//   z[i] = sum_k fu[k] * X[i-9+k],  X[2n] = x[n], X odd = 0, i in [0,266)
//   polyphase: i even -> odd taps, i odd -> even taps; local pairs (2a,2a+1)
//   share the same 6 input samples.
//   out[m] = sum_d fd[d] * z[2m+d], m in [0,128)
// Filters are symmetric so convolution == correlation.

#define BC   1024
#define IH   130
#define IW   130
#define OH   128
#define OW   128
#define TY   32
#define TX   32
#define ZI   74      // 2*TY + 10 (z rows needed per tile)
#define ZJ   74
#define XR   42      // TY + 10 (x rows needed per tile)
#define XC   42
#define AP   76      // padded stride for A buffer (z / x)
#define BP   76      // padded stride for B buffer (t)
#define UST  34      // padded stride for u inside B buffer (even -> float2 stores)
#define NTHREADS 256

__global__ __launch_bounds__(NTHREADS)
void flrelu_fused_kernel(const float* __restrict__ x,
                         const float* __restrict__ fup,
                         const float* __restrict__ fdn,
                         float* __restrict__ out)
{
    // A holds x tile, then z tile. B holds t tile, then u tile.
    __shared__ __align__(16) float A[ZI * AP];   // 74*76*4 = 22496 B
    __shared__ __align__(16) float Bm[XR * BP];  // 42*76*4 = 12768 B

    // Filters in registers. fu gets the per-dimension gain factor 2 (2*2 = up^2 = 4).
    float fu[12], fd[12];
#pragma unroll
    for (int k = 0; k < 12; k++) {
        fu[k] = fup[k] * 2.0f;
        fd[k] = fdn[k];
    }

    const int tile = blockIdx.x;          // 0..15  (4x4 tiles of 32x32)
    const int ch   = blockIdx.y;          // 0..1023
    const int m0   = (tile >> 2) * TY;    // output row origin
    const int n0   = (tile & 3) * TX;     // output col origin
    const int tid  = threadIdx.x;

    const float* xc = x + (size_t)ch * IH * IW;

    // ---- Stage 1: load x tile [42][42], zero-padded (rows m0-4.., cols n0-4..)
    for (int idx = tid; idx < XR * XC; idx += NTHREADS) {
        int r = idx / XC, c = idx % XC;
        int gr = m0 - 4 + r;
        int gc = n0 - 4 + c;
        float v = 0.0f;
        if ((unsigned)gr < IH && (unsigned)gc < IW) v = xc[gr * IW + gc];
        A[r * AP + c] = v;
    }
    __syncthreads();

    // ---- Stage 2: horizontal upsample-filter. t[r][2a] and t[r][2a+1]
    //      both read x[r][a..a+5]; even col -> taps fu[1,3,..11], odd -> fu[0,2,..10].
    for (int idx = tid; idx < XR * 37; idx += NTHREADS) {
        int r = idx / 37, a = idx % 37;
        const float* xr = &A[r * AP + a];
        float s0 = 0.0f, s1 = 0.0f;
#pragma unroll
        for (int s = 0; s < 6; s++) {
            float v = xr[s];
            s0 = fmaf(fu[1 + 2 * s], v, s0);
            s1 = fmaf(fu[2 * s],     v, s1);
        }
        Bm[r * BP + 2 * a]     = s0;
        Bm[r * BP + 2 * a + 1] = s1;
    }
    __syncthreads();

    // ---- Stage 3: vertical upsample-filter + leaky relu. z[2b][j], z[2b+1][j]
    //      both read t[b..b+5][j]. Overwrites A (x tile is dead).
    for (int idx = tid; idx < 37 * ZJ; idx += NTHREADS) {
        int b = idx / ZJ, j = idx % ZJ;
        float s0 = 0.0f, s1 = 0.0f;
#pragma unroll
        for (int s = 0; s < 6; s++) {
            float v = Bm[(b + s) * BP + j];
            s0 = fmaf(fu[1 + 2 * s], v, s0);
            s1 = fmaf(fu[2 * s],     v, s1);
        }
        s0 = (s0 >= 0.0f) ? s0 : 0.01f * s0;
        s1 = (s1 >= 0.0f) ? s1 : 0.01f * s1;
        A[(2 * b)     * AP + j] = s0;
        A[(2 * b + 1) * AP + j] = s1;
    }
    __syncthreads();

    // ---- Stage 4: horizontal downsample. u[i][2q], u[i][2q+1] read z[i][4q..4q+13].
    //      16B-aligned window (AP=76=4*19, 4q) -> LDS.128 x3 + LDS.64.
    //      Overwrites Bm (t tile is dead); u stored with stride UST=34.
    for (int idx = tid; idx < ZI * 16; idx += NTHREADS) {
        int i = idx / 16, q = idx % 16;
        const float4* z4 = reinterpret_cast<const float4*>(&A[i * AP + 4 * q]);
        float4 a0 = z4[0], a1 = z4[1], a2 = z4[2];
        float2 a3 = *reinterpret_cast<const float2*>(&A[i * AP + 4 * q + 12]);
        float v[14] = {a0.x, a0.y, a0.z, a0.w,
                       a1.x, a1.y, a1.z, a1.w,
                       a2.x, a2.y, a2.z, a2.w,
                       a3.x, a3.y};
        float s0 = 0.0f, s1 = 0.0f;
#pragma unroll
        for (int d = 0; d < 12; d++) {
            s0 = fmaf(fd[d], v[d],     s0);
            s1 = fmaf(fd[d], v[d + 2], s1);
        }
        *reinterpret_cast<float2*>(&Bm[i * UST + 2 * q]) = make_float2(s0, s1);
    }
    __syncthreads();

    // ---- Stage 5: vertical downsample + store. out rows (2mp, 2mp+1) share
    //      u rows [4mp .. 4mp+13].
    float* od = out + (size_t)ch * OH * OW;
    for (int idx = tid; idx < 16 * TX; idx += NTHREADS) {
        int mp = idx / TX, n = idx % TX;
        float v[14];
#pragma unroll
        for (int d = 0; d < 14; d++) v[d] = Bm[(4 * mp + d) * UST + n];
        float s0 = 0.0f, s1 = 0.0f;
#pragma unroll
        for (int d = 0; d < 12; d++) {
            s0 = fmaf(fd[d], v[d],     s0);
            s1 = fmaf(fd[d], v[d + 2], s1);
        }
        od[(m0 + 2 * mp)     * OW + (n0 + n)] = s0;
        od[(m0 + 2 * mp + 1) * OW + (n0 + n)] = s1;
    }
}

extern "C" void kernel_launch(void* const* d_in, const int* in_sizes, int n_in,
                              void* d_out, int out_size) {
    const float* x   = (const float*)d_in[0];
    const float* fup = (const float*)d_in[1];
    const float* fdn = (const float*)d_in[2];
    float* out = (float*)d_out;
    dim3 grid(16, BC);
    flrelu_fused_kernel<<<grid, NTHREADS>>>(x, fup, fdn, out);
}

// round 3
// speedup vs baseline: 1.2981x; 1.2981x over previous
#include <cuda_runtime.h>

// Fused FIR 2x-up -> lrelu(0.01) -> FIR 2x-down. Sliding-window version.
// x: [1024,130,130] f32, out: [1024,128,128] f32. 12-tap symmetric filters.

#define IH   130
#define IW   130
#define OH   128
#define OW   128
#define TY   32
#define TX   32
#define AP   76      // stride of A (x tile / z tile); mult of 4 for float4
#define BP   76      // stride of Bm (t tile)
#define UST  34      // stride of u inside Bm
#define NTHREADS 256

// up-pair from 6-sample window (w0..w5), 6 unique symmetric taps g0..g5:
//   even-row taps [fu1,fu3,fu5,fu7,fu9,fu11] = [g1,g3,g5,g4,g2,g0]
//   odd-row  taps [fu0,fu2,fu4,fu6,fu8,fu10] = [g0,g2,g4,g5,g3,g1]
#define UP_E(w0,w1,w2,w3,w4,w5) \
    fmaf(g0,(w5), fmaf(g2,(w4), fmaf(g4,(w3), fmaf(g5,(w2), fmaf(g3,(w1), g1*(w0))))))
#define UP_O(w0,w1,w2,w3,w4,w5) \
    fmaf(g1,(w5), fmaf(g3,(w4), fmaf(g5,(w3), fmaf(g4,(w2), fmaf(g2,(w1), g0*(w0))))))
// 12-tap down from v0..v11, symmetric taps e0..e5:
#define DN(v0,v1,v2,v3,v4,v5,v6,v7,v8,v9,v10,v11) \
    fmaf(e0,(v11), fmaf(e1,(v10), fmaf(e2,(v9), fmaf(e3,(v8), fmaf(e4,(v7), \
    fmaf(e5,(v6),  fmaf(e5,(v5),  fmaf(e4,(v4), fmaf(e3,(v3), fmaf(e2,(v2), \
    fmaf(e1,(v1),  e0*(v0))))))))))))

__global__ __launch_bounds__(NTHREADS)
void flrelu_fused_kernel(const float* __restrict__ x,
                         const float* __restrict__ fup,
                         const float* __restrict__ fdn,
                         float* __restrict__ out)
{
    // A: x tile [42x42] then z tile [74x74] (stride 76), +4 pad for fp4 slide.
    // Bm: t tile [42x76] then u tile [74 x stride 34]; 43 rows for slide overread.
    __shared__ __align__(16) float A[74 * AP + 4];
    __shared__ __align__(16) float Bm[43 * BP];

    // Symmetric filters: only first 6 taps needed. Up gets 2x gain per dim.
    const float g0 = fup[0] * 2.0f, g1 = fup[1] * 2.0f, g2 = fup[2] * 2.0f,
                g3 = fup[3] * 2.0f, g4 = fup[4] * 2.0f, g5 = fup[5] * 2.0f;
    const float e0 = fdn[0], e1 = fdn[1], e2 = fdn[2],
                e3 = fdn[3], e4 = fdn[4], e5 = fdn[5];

    const int tile = blockIdx.x;
    const int ch   = blockIdx.y;
    const int m0   = (tile >> 2) * TY;
    const int n0   = (tile & 3) * TX;
    const int tid  = threadIdx.x;

    const float* xc = x + (size_t)ch * IH * IW;

    // ---- Stage 1: load x tile [42][42] zero-padded
    for (int idx = tid; idx < 42 * 42; idx += NTHREADS) {
        int r = idx / 42, c = idx % 42;
        int gr = m0 - 4 + r, gc = n0 - 4 + c;
        float v = 0.0f;
        if ((unsigned)gr < IH && (unsigned)gc < IW) v = xc[gr * IW + gc];
        A[r * AP + c] = v;
    }
    __syncthreads();

    // ---- Stage 2: horizontal up. 42 rows x 6 segs; slide window of 6.
    if (tid < 252) {
        int r = tid / 6, s = tid % 6;
        int a0  = (s == 0) ? 0 : 6 * s + 1;        // seg starts 0,7,13,19,25,31
        int len = (s == 0) ? 7 : 6;                // covers a = 0..36
        const float* xr = &A[r * AP + a0];
        float w0 = xr[0], w1 = xr[1], w2 = xr[2], w3 = xr[3], w4 = xr[4], w5 = xr[5];
        float2* trow = reinterpret_cast<float2*>(&Bm[r * BP]) + a0;
#pragma unroll
        for (int k = 0; k < 7; k++) {
            if (k >= len) break;
            trow[k] = make_float2(UP_E(w0,w1,w2,w3,w4,w5), UP_O(w0,w1,w2,w3,w4,w5));
            float nw = xr[k + 6];                  // overreads into row pad: unused
            w0 = w1; w1 = w2; w2 = w3; w3 = w4; w4 = w5; w5 = nw;
        }
    }
    __syncthreads();

    // ---- Stage 3: vertical up + lrelu. 37 col-pairs x 6 segs; float2, slide 6.
    if (tid < 222) {
        int jp = tid % 37, seg = tid / 37;
        int b0  = (seg == 0) ? 0 : 6 * seg + 1;
        int len = (seg == 0) ? 7 : 6;              // covers b = 0..36
        const float2* tc = reinterpret_cast<const float2*>(&Bm[b0 * BP]) + jp;
        const int RS = BP / 2;                     // 38 float2 per row
        float2 w0 = tc[0], w1 = tc[RS], w2 = tc[2*RS], w3 = tc[3*RS],
               w4 = tc[4*RS], w5 = tc[5*RS];
        float* zc = &A[2 * jp];
#pragma unroll
        for (int k = 0; k < 7; k++) {
            if (k >= len) break;
            int b = b0 + k;
            float ex = UP_E(w0.x,w1.x,w2.x,w3.x,w4.x,w5.x);
            float ey = UP_E(w0.y,w1.y,w2.y,w3.y,w4.y,w5.y);
            float ox = UP_O(w0.x,w1.x,w2.x,w3.x,w4.x,w5.x);
            float oy = UP_O(w0.y,w1.y,w2.y,w3.y,w4.y,w5.y);
            ex = (ex >= 0.f) ? ex : 0.01f * ex;
            ey = (ey >= 0.f) ? ey : 0.01f * ey;
            ox = (ox >= 0.f) ? ox : 0.01f * ox;
            oy = (oy >= 0.f) ? oy : 0.01f * oy;
            *reinterpret_cast<float2*>(&zc[(2 * b) * AP])     = make_float2(ex, ey);
            *reinterpret_cast<float2*>(&zc[(2 * b + 1) * AP]) = make_float2(ox, oy);
            float2 nw = tc[(k + 6) * RS];          // row <= 42 (Bm has 43 rows)
            w0 = w1; w1 = w2; w2 = w3; w3 = w4; w4 = w5; w5 = nw;
        }
    }
    __syncthreads();

    // ---- Stage 4: horizontal down. 74 rows x 3 segs; float4 sliding window.
    if (tid < 222) {
        int i = tid % 74, seg = tid / 74;
        int q0  = (seg == 0) ? 0 : 6 + 5 * (seg - 1);   // 0,6,11
        int len = (seg == 0) ? 6 : 5;                   // covers q = 0..15
        const float4* zr = reinterpret_cast<const float4*>(&A[i * AP]) + q0;
        float4 w0 = zr[0], w1 = zr[1], w2 = zr[2], w3 = zr[3];
        float2* ur = reinterpret_cast<float2*>(&Bm[i * UST]);
#pragma unroll
        for (int k = 0; k < 6; k++) {
            if (k >= len) break;
            float s0 = DN(w0.x,w0.y,w0.z,w0.w, w1.x,w1.y,w1.z,w1.w, w2.x,w2.y,w2.z,w2.w);
            float s1 = DN(w0.z,w0.w, w1.x,w1.y,w1.z,w1.w, w2.x,w2.y,w2.z,w2.w, w3.x,w3.y);
            ur[q0 + k] = make_float2(s0, s1);
            float4 nw = zr[k + 4];                 // overread stays inside A (+4 pad)
            w0 = w1; w1 = w2; w2 = w3; w3 = nw;
        }
    }
    __syncthreads();

    // ---- Stage 5: vertical down + store. 32 cols x 8 segs; 2 row-pairs per seg.
    {
        int n = tid & 31, seg = tid >> 5;          // seg 0..7 -> mp = 2*seg, 2*seg+1
        int mp0 = 2 * seg;
        const float* uc = &Bm[n];
        float v[18];
#pragma unroll
        for (int d = 0; d < 14; d++) v[d] = uc[(4 * mp0 + d) * UST];
        float s0 = DN(v[0],v[1],v[2],v[3],v[4],v[5],v[6],v[7],v[8],v[9],v[10],v[11]);
        float s1 = DN(v[2],v[3],v[4],v[5],v[6],v[7],v[8],v[9],v[10],v[11],v[12],v[13]);
        float* od = out + (size_t)ch * OH * OW + (size_t)(m0 + 2 * mp0) * OW + n0 + n;
        od[0]  = s0;
        od[OW] = s1;
#pragma unroll
        for (int d = 14; d < 18; d++) v[d] = uc[(4 * mp0 + d) * UST];
        float s2 = DN(v[4],v[5],v[6],v[7],v[8],v[9],v[10],v[11],v[12],v[13],v[14],v[15]);
        float s3 = DN(v[6],v[7],v[8],v[9],v[10],v[11],v[12],v[13],v[14],v[15],v[16],v[17]);
        od[2 * OW] = s2;
        od[3 * OW] = s3;
    }
}

extern "C" void kernel_launch(void* const* d_in, const int* in_sizes, int n_in,
                              void* d_out, int out_size) {
    const float* x   = (const float*)d_in[0];
    const float* fup = (const float*)d_in[1];
    const float* fdn = (const float*)d_in[2];
    float* out = (float*)d_out;
    dim3 grid(16, 1024);
    flrelu_fused_kernel<<<grid, NTHREADS>>>(x, fup, fdn, out);
}

// round 4
// speedup vs baseline: 2.0607x; 1.5875x over previous
#include <cuda_runtime.h>

// Fused filtered-lrelu, pipeline reordered: up-H -> (up-V + lrelu + down-V
// fused per-column in registers, z never hits smem) -> down-H.
// x: [1024,130,130] f32, out: [1024,128,128] f32, 12-tap symmetric filters.

#define IH   130
#define IW   130
#define OW   128
#define TP   78      // stride of t tile [42 rows x 74 cols]
#define WP   76      // stride of w tile [32 rows x 74 cols] (mult of 4 for float4)
#define NTHREADS 256

// up-pair from 6-sample window, 6 unique symmetric taps g0..g5:
//   even phase taps [fu1,fu3,fu5,fu7,fu9,fu11] = [g1,g3,g5,g4,g2,g0]
//   odd  phase taps [fu0,fu2,fu4,fu6,fu8,fu10] = [g0,g2,g4,g5,g3,g1]
#define UP_E(w0,w1,w2,w3,w4,w5) \
    fmaf(g0,(w5), fmaf(g2,(w4), fmaf(g4,(w3), fmaf(g5,(w2), fmaf(g3,(w1), g1*(w0))))))
#define UP_O(w0,w1,w2,w3,w4,w5) \
    fmaf(g1,(w5), fmaf(g3,(w4), fmaf(g5,(w3), fmaf(g4,(w2), fmaf(g2,(w1), g0*(w0))))))
// 12-tap symmetric down filter over v0..v11:
#define DN(v0,v1,v2,v3,v4,v5,v6,v7,v8,v9,v10,v11) \
    fmaf(e0,(v11), fmaf(e1,(v10), fmaf(e2,(v9), fmaf(e3,(v8), fmaf(e4,(v7), \
    fmaf(e5,(v6),  fmaf(e5,(v5),  fmaf(e4,(v4), fmaf(e3,(v3), fmaf(e2,(v2), \
    fmaf(e1,(v1),  e0*(v0))))))))))))

__global__ __launch_bounds__(NTHREADS)
void flrelu_fused_kernel(const float* __restrict__ x,
                         const float* __restrict__ fup,
                         const float* __restrict__ fdn,
                         float* __restrict__ out)
{
    __shared__ __align__(16) float t[42 * TP];   // up-H result      (12.2 KB)
    __shared__ __align__(16) float w[32 * WP];   // down-V result    ( 9.7 KB)

    const float g0 = fup[0] * 2.0f, g1 = fup[1] * 2.0f, g2 = fup[2] * 2.0f,
                g3 = fup[3] * 2.0f, g4 = fup[4] * 2.0f, g5 = fup[5] * 2.0f;
    const float e0 = fdn[0], e1 = fdn[1], e2 = fdn[2],
                e3 = fdn[3], e4 = fdn[4], e5 = fdn[5];

    const int tile = blockIdx.x;
    const int ch   = blockIdx.y;
    const int m0   = (tile >> 2) * 32;
    const int n0   = (tile & 3) * 32;
    const int tid  = threadIdx.x;

    // ---- Stage A: horizontal 2x-up straight from gmem.
    // 42 rows x 6 overlapping segments (7 output-pairs each). Thread (r,s)
    // reads x[r][6s-4 .. 6s+8] (13 predicated loads) and writes t cols 12s..12s+13.
    if (tid < 252) {
        const int r = tid / 6, s = tid % 6;
        const int gr  = m0 - 4 + r;
        const int gc0 = n0 - 4 + 6 * s;
        const bool rok = (unsigned)gr < (unsigned)IH;
        const float* xrow = x + (size_t)ch * IH * IW + gr * IW + gc0;
        float xa[13];
#pragma unroll
        for (int k = 0; k < 13; k++) {
            bool ok = rok && ((unsigned)(gc0 + k) < (unsigned)IW);
            xa[k] = ok ? xrow[k] : 0.0f;
        }
        float2* trow = reinterpret_cast<float2*>(t + r * TP) + 6 * s;
#pragma unroll
        for (int k = 0; k < 7; k++) {
            trow[k] = make_float2(UP_E(xa[k],xa[k+1],xa[k+2],xa[k+3],xa[k+4],xa[k+5]),
                                  UP_O(xa[k],xa[k+1],xa[k+2],xa[k+3],xa[k+4],xa[k+5]));
        }
    }
    __syncthreads();

    // ---- Stage B: per-column vertical up + lrelu + vertical down, fused.
    // 74 cols x 2 row-segments (16 outputs each). Thread preloads its 26 t
    // samples, then 21 transposed-polyphase steps: z-pair (2b,2b+1) generated,
    // lrelu'd, pushed into 6 rolling accumulators; acc[0] completes each step.
    if (tid < 148) {
        const int seg = (tid >= 74) ? 1 : 0;
        const int j   = tid - 74 * seg;
        const int mb  = seg << 4;                  // 0 or 16
        const float* tc = t + mb * TP + j;
        float win[26];
#pragma unroll
        for (int i = 0; i < 26; i++) win[i] = tc[i * TP];
        float acc0 = 0.f, acc1 = 0.f, acc2 = 0.f, acc3 = 0.f, acc4 = 0.f, acc5 = 0.f;
        float* wc = w + j;
#pragma unroll
        for (int k = 0; k < 21; k++) {
            float ze = UP_E(win[k],win[k+1],win[k+2],win[k+3],win[k+4],win[k+5]);
            float zo = UP_O(win[k],win[k+1],win[k+2],win[k+3],win[k+4],win[k+5]);
            ze = (ze >= 0.f) ? ze : 0.01f * ze;
            zo = (zo >= 0.f) ? zo : 0.01f * zo;
            // output m = b-5+r gets fd[2(b-m)]*ze + fd[2(b-m)+1]*zo
            acc0 = fmaf(e1, ze, fmaf(e0, zo, acc0));
            acc1 = fmaf(e3, ze, fmaf(e2, zo, acc1));
            acc2 = fmaf(e5, ze, fmaf(e4, zo, acc2));
            acc3 = fmaf(e4, ze, fmaf(e5, zo, acc3));
            acc4 = fmaf(e2, ze, fmaf(e3, zo, acc4));
            acc5 = fmaf(e0, ze, fmaf(e1, zo, acc5));
            if (k >= 5) wc[(mb + k - 5) * WP] = acc0;
            acc0 = acc1; acc1 = acc2; acc2 = acc3; acc3 = acc4; acc4 = acc5;
            acc5 = 0.f;
        }
    }
    __syncthreads();

    // ---- Stage C: horizontal down + store. Thread (m, s) computes out cols
    // 4s..4s+3 of row m from w[m][8s..8s+17] (5 float4 loads), float4 store.
    {
        const int m = tid >> 3, s = tid & 7;
        const float4* wr = reinterpret_cast<const float4*>(w + m * WP) + 2 * s;
        float4 q0 = wr[0], q1 = wr[1], q2 = wr[2], q3 = wr[3], q4 = wr[4];
        float v0=q0.x,v1=q0.y,v2=q0.z,v3=q0.w,
              v4=q1.x,v5=q1.y,v6=q1.z,v7=q1.w,
              v8=q2.x,v9=q2.y,v10=q2.z,v11=q2.w,
              v12=q3.x,v13=q3.y,v14=q3.z,v15=q3.w,
              v16=q4.x,v17=q4.y;
        float o0 = DN(v0,v1,v2,v3,v4,v5,v6,v7,v8,v9,v10,v11);
        float o1 = DN(v2,v3,v4,v5,v6,v7,v8,v9,v10,v11,v12,v13);
        float o2 = DN(v4,v5,v6,v7,v8,v9,v10,v11,v12,v13,v14,v15);
        float o3 = DN(v6,v7,v8,v9,v10,v11,v12,v13,v14,v15,v16,v17);
        float* od = out + (size_t)ch * OW * OW + (size_t)(m0 + m) * OW + n0 + 4 * s;
        *reinterpret_cast<float4*>(od) = make_float4(o0, o1, o2, o3);
    }
}

extern "C" void kernel_launch(void* const* d_in, const int* in_sizes, int n_in,
                              void* d_out, int out_size) {
    const float* x   = (const float*)d_in[0];
    const float* fup = (const float*)d_in[1];
    const float* fdn = (const float*)d_in[2];
    float* out = (float*)d_out;
    dim3 grid(16, 1024);
    flrelu_fused_kernel<<<grid, NTHREADS>>>(x, fup, fdn, out);
}